// round 1
// baseline (speedup 1.0000x reference)
#include <cuda_runtime.h>
#include <cstdint>

// ---------------------------------------------------------------------------
// PrismDecoder: gather-mean -> 4-layer MLP -> 3x3 special procrustes ->
// rigid transform -> segment-mean.
// Round 1: fp32 everywhere (establish correctness + rel_err headroom).
// ---------------------------------------------------------------------------

#define N_VERTS 100000
#define N_FACES 200000
#define DIMD    512

// ---- static scratch (no allocation allowed) ----
__device__ float g_bufA[(size_t)N_FACES * 512];   // face_feat / h2
__device__ float g_bufB[(size_t)N_FACES * 512];   // h1
__device__ float g_h3  [(size_t)N_FACES * 256];   // h3
__device__ float g_out12[(size_t)N_FACES * 12];   // out12
__device__ float g_summed[(size_t)N_VERTS * 3];
__device__ float g_counts[(size_t)N_VERTS];

__device__ __forceinline__ float* devbuf(int sel) {
    switch (sel) {
        case 0: return g_bufA;
        case 1: return g_bufB;
        case 2: return g_h3;
        default: return g_out12;
    }
}

// ---------------------------------------------------------------------------
// K_init: zero segment accumulators
// ---------------------------------------------------------------------------
__global__ void zero_kernel() {
    int i = blockIdx.x * blockDim.x + threadIdx.x;
    if (i < N_VERTS * 3) g_summed[i] = 0.0f;
    if (i < N_VERTS)     g_counts[i] = 0.0f;
}

// ---------------------------------------------------------------------------
// K0: face_feat[f] = mean of 3 gathered feature rows  (writes g_bufA)
// one thread per (face, float4-chunk); 128 chunks per face
// ---------------------------------------------------------------------------
__global__ void gather_kernel(const float* __restrict__ features,
                              const int*   __restrict__ faces) {
    int idx = blockIdx.x * blockDim.x + threadIdx.x;      // 0 .. 25,599,999
    int f  = idx >> 7;
    int c4 = (idx & 127) << 2;
    if (f >= N_FACES) return;
    int i0 = __ldg(&faces[f * 3 + 0]);
    int i1 = __ldg(&faces[f * 3 + 1]);
    int i2 = __ldg(&faces[f * 3 + 2]);
    float4 a = *(const float4*)&features[(size_t)i0 * DIMD + c4];
    float4 b = *(const float4*)&features[(size_t)i1 * DIMD + c4];
    float4 c = *(const float4*)&features[(size_t)i2 * DIMD + c4];
    const float k = 1.0f / 3.0f;
    float4 r;
    r.x = (a.x + b.x + c.x) * k;
    r.y = (a.y + b.y + c.y) * k;
    r.z = (a.z + b.z + c.z) * k;
    r.w = (a.w + b.w + c.w) * k;
    *(float4*)&g_bufA[(size_t)f * DIMD + c4] = r;
}

// ---------------------------------------------------------------------------
// Tiled fp32 SGEMM: C = relu?(A @ W + bias), A: MxK row-major, W: KxN row-major
// BM=128 BN=128 BK=16, 256 threads, 8x8 micro-tile
// ---------------------------------------------------------------------------
#define BM 128
#define BN 128
#define BK 16
#define TM 8
#define TN 8

__global__ __launch_bounds__(256)
void sgemm_bias_act(int srcSel, int dstSel,
                    const float* __restrict__ W,
                    const float* __restrict__ bias,
                    int M, int N, int K, int doRelu) {
    const float* __restrict__ A = devbuf(srcSel);
    float* __restrict__ C = devbuf(dstSel);

    __shared__ float As[BK][BM];
    __shared__ float Bs[BK][BN];

    const int bm = blockIdx.y * BM;
    const int bn = blockIdx.x * BN;
    const int tid = threadIdx.x;
    const int tx = tid & 15;   // n-tile
    const int ty = tid >> 4;   // m-tile

    float acc[TM][TN];
    #pragma unroll
    for (int i = 0; i < TM; i++)
        #pragma unroll
        for (int j = 0; j < TN; j++) acc[i][j] = 0.0f;

    for (int k0 = 0; k0 < K; k0 += BK) {
        // load A tile (BM x BK), transposed into As[k][m]
        #pragma unroll
        for (int i = 0; i < 2; i++) {
            int g = tid + i * 256;          // 0..511
            int r  = g >> 2;                // 0..127
            int kc = (g & 3) << 2;          // 0,4,8,12
            int grow = bm + r;
            float4 v = make_float4(0.f, 0.f, 0.f, 0.f);
            if (grow < M)
                v = *(const float4*)&A[(size_t)grow * K + k0 + kc];
            As[kc + 0][r] = v.x;
            As[kc + 1][r] = v.y;
            As[kc + 2][r] = v.z;
            As[kc + 3][r] = v.w;
        }
        // load B tile (BK x BN)
        #pragma unroll
        for (int i = 0; i < 2; i++) {
            int g = tid + i * 256;
            int r  = g >> 5;                // 0..15
            int nc = (g & 31) << 2;         // 0..124
            *(float4*)&Bs[r][nc] =
                *(const float4*)&W[(size_t)(k0 + r) * N + bn + nc];
        }
        __syncthreads();

        #pragma unroll
        for (int k = 0; k < BK; k++) {
            float a[TM], b[TN];
            float4 a0 = *(const float4*)&As[k][ty * TM];
            float4 a1 = *(const float4*)&As[k][ty * TM + 4];
            a[0]=a0.x; a[1]=a0.y; a[2]=a0.z; a[3]=a0.w;
            a[4]=a1.x; a[5]=a1.y; a[6]=a1.z; a[7]=a1.w;
            float4 b0 = *(const float4*)&Bs[k][tx * TN];
            float4 b1 = *(const float4*)&Bs[k][tx * TN + 4];
            b[0]=b0.x; b[1]=b0.y; b[2]=b0.z; b[3]=b0.w;
            b[4]=b1.x; b[5]=b1.y; b[6]=b1.z; b[7]=b1.w;
            #pragma unroll
            for (int i = 0; i < TM; i++)
                #pragma unroll
                for (int j = 0; j < TN; j++)
                    acc[i][j] = fmaf(a[i], b[j], acc[i][j]);
        }
        __syncthreads();
    }

    // epilogue
    #pragma unroll
    for (int i = 0; i < TM; i++) {
        int gr = bm + ty * TM + i;
        if (gr >= M) continue;
        #pragma unroll
        for (int j = 0; j < TN; j++) {
            int gc = bn + tx * TN + j;
            float v = acc[i][j] + bias[gc];
            if (doRelu) v = fmaxf(v, 0.0f);
            C[(size_t)gr * N + gc] = v;
        }
    }
}

// ---------------------------------------------------------------------------
// K4: out12 = h3 @ W4 + b4   (M x 256 x 12, no relu). One thread per row.
// ---------------------------------------------------------------------------
__global__ __launch_bounds__(128)
void out12_kernel(const float* __restrict__ W4, const float* __restrict__ b4) {
    __shared__ float ws[256 * 12];
    for (int i = threadIdx.x; i < 256 * 12; i += blockDim.x) ws[i] = W4[i];
    __syncthreads();
    int r = blockIdx.x * blockDim.x + threadIdx.x;
    if (r >= N_FACES) return;
    const float* x = g_h3 + (size_t)r * 256;
    float acc[12];
    #pragma unroll
    for (int n = 0; n < 12; n++) acc[n] = b4[n];
    for (int k = 0; k < 256; k += 4) {
        float4 xv = *(const float4*)&x[k];
        #pragma unroll
        for (int n = 0; n < 12; n++) {
            acc[n] = fmaf(xv.x, ws[(k + 0) * 12 + n], acc[n]);
            acc[n] = fmaf(xv.y, ws[(k + 1) * 12 + n], acc[n]);
            acc[n] = fmaf(xv.z, ws[(k + 2) * 12 + n], acc[n]);
            acc[n] = fmaf(xv.w, ws[(k + 3) * 12 + n], acc[n]);
        }
    }
    #pragma unroll
    for (int n = 0; n < 12; n++) g_out12[(size_t)r * 12 + n] = acc[n];
}

// ---------------------------------------------------------------------------
// Jacobi rotation for symmetric 3x3, zeroing A[p][q]; V accumulates (columns
// become eigenvectors).  Numerical-Recipes convention.
// ---------------------------------------------------------------------------
__device__ __forceinline__ void jrot(float A[3][3], float V[3][3],
                                     int p, int q, int r) {
    float apq = A[p][q];
    if (fabsf(apq) < 1e-20f) return;
    float tau = (A[q][q] - A[p][p]) / (2.0f * apq);
    float t = copysignf(1.0f, tau) / (fabsf(tau) + sqrtf(1.0f + tau * tau));
    float c = rsqrtf(1.0f + t * t);
    float s = t * c;
    A[p][p] -= t * apq;
    A[q][q] += t * apq;
    A[p][q] = 0.0f; A[q][p] = 0.0f;
    float arp = A[r][p], arq = A[r][q];
    A[r][p] = c * arp - s * arq; A[p][r] = A[r][p];
    A[r][q] = s * arp + c * arq; A[q][r] = A[r][q];
    #pragma unroll
    for (int k = 0; k < 3; k++) {
        float vkp = V[k][p], vkq = V[k][q];
        V[k][p] = c * vkp - s * vkq;
        V[k][q] = s * vkp + c * vkq;
    }
}

__device__ __forceinline__ void cross3(const float a[3], const float b[3], float o[3]) {
    o[0] = a[1] * b[2] - a[2] * b[1];
    o[1] = a[2] * b[0] - a[0] * b[2];
    o[2] = a[0] * b[1] - a[1] * b[0];
}

// ---------------------------------------------------------------------------
// K5: per-face special procrustes + rigid transform + atomic segment sums.
// R = u1 v1^T + u2 v2^T + (u1 x u2)(v1 x v2)^T   ==  U diag(1,1,det(UV^T)) V^T
// ---------------------------------------------------------------------------
__global__ __launch_bounds__(256)
void procrustes_kernel(const float* __restrict__ verts,
                       const int*   __restrict__ faces,
                       float* __restrict__ out) {
    int f = blockIdx.x * blockDim.x + threadIdx.x;
    if (f >= N_FACES) return;

    float o[12];
    #pragma unroll
    for (int i = 0; i < 12; i++) o[i] = g_out12[(size_t)f * 12 + i];

    float m[3][3];
    #pragma unroll
    for (int i = 0; i < 3; i++)
        #pragma unroll
        for (int j = 0; j < 3; j++) m[i][j] = o[3 * i + j];

    // normalize scale (R invariant under positive scaling; improves conditioning)
    float fr = 0.0f;
    #pragma unroll
    for (int i = 0; i < 3; i++)
        #pragma unroll
        for (int j = 0; j < 3; j++) fr += m[i][j] * m[i][j];
    float inv = rsqrtf(fmaxf(fr, 1e-30f));
    #pragma unroll
    for (int i = 0; i < 3; i++)
        #pragma unroll
        for (int j = 0; j < 3; j++) m[i][j] *= inv;

    // A = m^T m
    float A[3][3];
    #pragma unroll
    for (int i = 0; i < 3; i++)
        #pragma unroll
        for (int j = 0; j < 3; j++) {
            float s = 0.0f;
            #pragma unroll
            for (int k = 0; k < 3; k++) s += m[k][i] * m[k][j];
            A[i][j] = s;
        }
    float V[3][3] = {{1,0,0},{0,1,0},{0,0,1}};

    #pragma unroll
    for (int sweep = 0; sweep < 6; sweep++) {
        jrot(A, V, 0, 1, 2);
        jrot(A, V, 0, 2, 1);
        jrot(A, V, 1, 2, 0);
    }

    float w0 = A[0][0], w1 = A[1][1], w2 = A[2][2];
    int imax = (w0 >= w1) ? (w0 >= w2 ? 0 : 2) : (w1 >= w2 ? 1 : 2);
    int imin = (w0 <= w1) ? (w0 <= w2 ? 0 : 2) : (w1 <= w2 ? 1 : 2);
    if (imax == imin) imin = (imax + 1) % 3;   // all-equal degenerate
    int imid = 3 - imax - imin;

    float v1[3] = {V[0][imax], V[1][imax], V[2][imax]};
    float v2[3] = {V[0][imid], V[1][imid], V[2][imid]};

    // u1 = normalize(m v1)
    float u1[3], u2[3];
    #pragma unroll
    for (int a = 0; a < 3; a++)
        u1[a] = m[a][0] * v1[0] + m[a][1] * v1[1] + m[a][2] * v1[2];
    float n1 = sqrtf(u1[0]*u1[0] + u1[1]*u1[1] + u1[2]*u1[2]);
    if (n1 > 1e-12f) {
        float in1 = 1.0f / n1;
        u1[0] *= in1; u1[1] *= in1; u1[2] *= in1;
    } else { u1[0] = 1.0f; u1[1] = 0.0f; u1[2] = 0.0f; }

    // u2 = normalize(m v2 orthogonalized against u1)
    #pragma unroll
    for (int a = 0; a < 3; a++)
        u2[a] = m[a][0] * v2[0] + m[a][1] * v2[1] + m[a][2] * v2[2];
    float d = u2[0]*u1[0] + u2[1]*u1[1] + u2[2]*u1[2];
    u2[0] -= d * u1[0]; u2[1] -= d * u1[1]; u2[2] -= d * u1[2];
    float n2 = sqrtf(u2[0]*u2[0] + u2[1]*u2[1] + u2[2]*u2[2]);
    if (n2 > 1e-10f) {
        float in2 = 1.0f / n2;
        u2[0] *= in2; u2[1] *= in2; u2[2] *= in2;
    } else {
        float e[3] = {0.f, 0.f, 0.f};
        e[(fabsf(u1[0]) < 0.9f) ? 0 : 1] = 1.0f;
        cross3(u1, e, u2);
        float nn = rsqrtf(fmaxf(u2[0]*u2[0]+u2[1]*u2[1]+u2[2]*u2[2], 1e-30f));
        u2[0] *= nn; u2[1] *= nn; u2[2] *= nn;
    }

    float u3[3], v3[3];
    cross3(u1, u2, u3);
    cross3(v1, v2, v3);

    float R[3][3];
    #pragma unroll
    for (int a = 0; a < 3; a++)
        #pragma unroll
        for (int b = 0; b < 3; b++)
            R[a][b] = u1[a]*v1[b] + u2[a]*v2[b] + u3[a]*v3[b];

    // outputs: rotations
    float* rot_out = out + (size_t)(N_VERTS * 3) + (size_t)N_FACES * 9 + (size_t)f * 9;
    #pragma unroll
    for (int a = 0; a < 3; a++)
        #pragma unroll
        for (int b = 0; b < 3; b++)
            rot_out[a * 3 + b] = R[a][b];

    // transformed prism + segment atomics
    float t0 = o[9], t1 = o[10], t2 = o[11];
    float* tp_out = out + (size_t)(N_VERTS * 3) + (size_t)f * 9;
    #pragma unroll
    for (int j = 0; j < 3; j++) {
        int vi = faces[f * 3 + j];
        float p0 = verts[(size_t)vi * 3 + 0];
        float p1 = verts[(size_t)vi * 3 + 1];
        float p2 = verts[(size_t)vi * 3 + 2];
        float tpx = p0 * R[0][0] + p1 * R[1][0] + p2 * R[2][0] + t0;
        float tpy = p0 * R[0][1] + p1 * R[1][1] + p2 * R[2][1] + t1;
        float tpz = p0 * R[0][2] + p1 * R[1][2] + p2 * R[2][2] + t2;
        tp_out[j * 3 + 0] = tpx;
        tp_out[j * 3 + 1] = tpy;
        tp_out[j * 3 + 2] = tpz;
        atomicAdd(&g_summed[(size_t)vi * 3 + 0], tpx);
        atomicAdd(&g_summed[(size_t)vi * 3 + 1], tpy);
        atomicAdd(&g_summed[(size_t)vi * 3 + 2], tpz);
        atomicAdd(&g_counts[vi], 1.0f);
    }
}

// ---------------------------------------------------------------------------
// K6: vfeat = summed / max(counts, 1)
// ---------------------------------------------------------------------------
__global__ void finalize_kernel(float* __restrict__ out) {
    int v = blockIdx.x * blockDim.x + threadIdx.x;
    if (v >= N_VERTS) return;
    float c = fmaxf(g_counts[v], 1.0f);
    float ic = 1.0f / c;
    out[(size_t)v * 3 + 0] = g_summed[(size_t)v * 3 + 0] * ic;
    out[(size_t)v * 3 + 1] = g_summed[(size_t)v * 3 + 1] * ic;
    out[(size_t)v * 3 + 2] = g_summed[(size_t)v * 3 + 2] * ic;
}

// ---------------------------------------------------------------------------
extern "C" void kernel_launch(void* const* d_in, const int* in_sizes, int n_in,
                              void* d_out, int out_size) {
    const float* verts    = (const float*)d_in[0];
    const float* features = (const float*)d_in[1];
    const int*   faces    = (const int*)  d_in[2];
    const float* W1 = (const float*)d_in[3];
    const float* b1 = (const float*)d_in[4];
    const float* W2 = (const float*)d_in[5];
    const float* b2 = (const float*)d_in[6];
    const float* W3 = (const float*)d_in[7];
    const float* b3 = (const float*)d_in[8];
    const float* W4 = (const float*)d_in[9];
    const float* b4 = (const float*)d_in[10];
    float* out = (float*)d_out;

    (void)in_sizes; (void)n_in; (void)out_size;

    // zero segment accumulators
    zero_kernel<<<(N_VERTS * 3 + 255) / 256, 256>>>();

    // face features
    {
        int total = N_FACES * 128;
        gather_kernel<<<(total + 255) / 256, 256>>>(features, faces);
    }

    const int M = N_FACES;
    dim3 block(256);

    // h1 = relu(face_feat @ W1 + b1)   : A=bufA -> bufB
    sgemm_bias_act<<<dim3(512 / BN, (M + BM - 1) / BM), block>>>(
        0, 1, W1, b1, M, 512, 512, 1);
    // h2 = relu(h1 @ W2 + b2)          : bufB -> bufA
    sgemm_bias_act<<<dim3(512 / BN, (M + BM - 1) / BM), block>>>(
        1, 0, W2, b2, M, 512, 512, 1);
    // h3 = relu(h2 @ W3 + b3)          : bufA -> g_h3
    sgemm_bias_act<<<dim3(256 / BN, (M + BM - 1) / BM), block>>>(
        0, 2, W3, b3, M, 256, 512, 1);

    // out12 = h3 @ W4 + b4
    out12_kernel<<<(M + 127) / 128, 128>>>(W4, b4);

    // procrustes + transform + segment sums
    procrustes_kernel<<<(M + 255) / 256, 256>>>(verts, faces, out);

    // vertex means
    finalize_kernel<<<(N_VERTS + 255) / 256, 256>>>(out);
}

// round 3
// speedup vs baseline: 2.5802x; 2.5802x over previous
#include <cuda_runtime.h>
#include <cuda_bf16.h>
#include <cstdint>

// ===========================================================================
// PrismDecoder round 3: mma.sync (baseline PTX, fallback HMMA) split-bf16
// GEMMs. tcgen05 is unavailable: harness ptxas target is sm_103 (no 'a').
//   gather-mean (bf16 hi/lo) -> 3x [HMMA GEMM + bias + relu, hi/lo out]
//   -> out12 (fp32) -> procrustes -> transform -> segment mean
// ===========================================================================

#define N_VERTS 100000
#define N_FACES 200000
#define MPAD    200064            // 1563 * 128
#define DIMD    512

// -------------------- static device scratch (no allocs) --------------------
__device__ __nv_bfloat16 g_AH0[(size_t)MPAD * 512];
__device__ __nv_bfloat16 g_AL0[(size_t)MPAD * 512];
__device__ __nv_bfloat16 g_AH1[(size_t)MPAD * 512];
__device__ __nv_bfloat16 g_AL1[(size_t)MPAD * 512];
__device__ __nv_bfloat16 g_H3H[(size_t)MPAD * 256];
__device__ __nv_bfloat16 g_H3L[(size_t)MPAD * 256];
// transposed weights [N][K] bf16 hi/lo
__device__ __nv_bfloat16 g_W1H[512 * 512];
__device__ __nv_bfloat16 g_W1L[512 * 512];
__device__ __nv_bfloat16 g_W2H[512 * 512];
__device__ __nv_bfloat16 g_W2L[512 * 512];
__device__ __nv_bfloat16 g_W3H[256 * 512];
__device__ __nv_bfloat16 g_W3L[256 * 512];
__device__ float g_out12[(size_t)N_FACES * 12];
__device__ float g_summed[(size_t)N_VERTS * 3];
__device__ float g_counts[N_VERTS];

__device__ __forceinline__ __nv_bfloat16* bsel(int s) {
    switch (s) {
        case 0:  return g_AH0;  case 1:  return g_AL0;
        case 2:  return g_AH1;  case 3:  return g_AL1;
        case 4:  return g_H3H;  case 5:  return g_H3L;
        case 6:  return g_W1H;  case 7:  return g_W1L;
        case 8:  return g_W2H;  case 9:  return g_W2L;
        case 10: return g_W3H;  default: return g_W3L;
    }
}

// -------------------- PTX helpers (baseline ISA only) --------------------
__device__ __forceinline__ uint32_t smem_u32(const void* p) {
    uint32_t a;
    asm("{ .reg .u64 t; cvta.to.shared.u64 t, %1; cvt.u32.u64 %0, t; }"
        : "=r"(a) : "l"(p));
    return a;
}

__device__ __forceinline__ void cp16(uint32_t dst, const void* src) {
    asm volatile("cp.async.cg.shared.global [%0], [%1], 16;"
                 :: "r"(dst), "l"(src));
}
#define CP_COMMIT() asm volatile("cp.async.commit_group;" ::: "memory")
#define CP_WAIT(n)  asm volatile("cp.async.wait_group %0;" :: "n"(n) : "memory")

__device__ __forceinline__ void ldmx4(uint32_t r[4], uint32_t addr) {
    asm volatile("ldmatrix.sync.aligned.m8n8.x4.shared.b16 {%0,%1,%2,%3}, [%4];"
                 : "=r"(r[0]), "=r"(r[1]), "=r"(r[2]), "=r"(r[3]) : "r"(addr));
}
__device__ __forceinline__ void ldmx2(uint32_t r[2], uint32_t addr) {
    asm volatile("ldmatrix.sync.aligned.m8n8.x2.shared.b16 {%0,%1}, [%2];"
                 : "=r"(r[0]), "=r"(r[1]) : "r"(addr));
}
__device__ __forceinline__ void mma16816(float d[4], const uint32_t a[4],
                                         const uint32_t b[2]) {
    asm volatile(
        "mma.sync.aligned.m16n8k16.row.col.f32.bf16.bf16.f32 "
        "{%0,%1,%2,%3}, {%4,%5,%6,%7}, {%8,%9}, {%0,%1,%2,%3};"
        : "+f"(d[0]), "+f"(d[1]), "+f"(d[2]), "+f"(d[3])
        : "r"(a[0]), "r"(a[1]), "r"(a[2]), "r"(a[3]), "r"(b[0]), "r"(b[1]));
}

__device__ __forceinline__ uint32_t packbf2(__nv_bfloat16 a, __nv_bfloat16 b) {
    return (uint32_t)__bfloat16_as_ushort(a) |
           ((uint32_t)__bfloat16_as_ushort(b) << 16);
}

// ---------------------------------------------------------------------------
__global__ void zero_kernel() {
    int i = blockIdx.x * blockDim.x + threadIdx.x;
    if (i < N_VERTS * 3) g_summed[i] = 0.0f;
    if (i < N_VERTS)     g_counts[i] = 0.0f;
}

// weight transpose + hi/lo split:  W [K][N] fp32 -> Wt [N][K] bf16 hi/lo
__global__ void convert_w(const float* __restrict__ W, int selH, int selL, int N) {
    int idx = blockIdx.x * blockDim.x + threadIdx.x;     // n*512 + k
    if (idx >= N * 512) return;
    int n = idx >> 9, k = idx & 511;
    float v = W[(size_t)k * N + n];
    __nv_bfloat16 h = __float2bfloat16(v);
    bsel(selH)[idx] = h;
    bsel(selL)[idx] = __float2bfloat16(v - __bfloat162float(h));
}

// gather-mean -> bf16 hi/lo split into A0
__global__ void gather_kernel(const float* __restrict__ features,
                              const int*   __restrict__ faces) {
    int idx = blockIdx.x * blockDim.x + threadIdx.x;
    int f  = idx >> 7;
    int c4 = (idx & 127) << 2;
    if (f >= N_FACES) return;
    int i0 = __ldg(&faces[f * 3 + 0]);
    int i1 = __ldg(&faces[f * 3 + 1]);
    int i2 = __ldg(&faces[f * 3 + 2]);
    float4 a = *(const float4*)&features[(size_t)i0 * DIMD + c4];
    float4 b = *(const float4*)&features[(size_t)i1 * DIMD + c4];
    float4 c = *(const float4*)&features[(size_t)i2 * DIMD + c4];
    const float k = 1.0f / 3.0f;
    float v[4];
    v[0] = (a.x + b.x + c.x) * k;
    v[1] = (a.y + b.y + c.y) * k;
    v[2] = (a.z + b.z + c.z) * k;
    v[3] = (a.w + b.w + c.w) * k;
    __nv_bfloat16 h0 = __float2bfloat16(v[0]);
    __nv_bfloat16 h1 = __float2bfloat16(v[1]);
    __nv_bfloat16 h2 = __float2bfloat16(v[2]);
    __nv_bfloat16 h3 = __float2bfloat16(v[3]);
    __nv_bfloat16 l0 = __float2bfloat16(v[0] - __bfloat162float(h0));
    __nv_bfloat16 l1 = __float2bfloat16(v[1] - __bfloat162float(h1));
    __nv_bfloat16 l2 = __float2bfloat16(v[2] - __bfloat162float(h2));
    __nv_bfloat16 l3 = __float2bfloat16(v[3] - __bfloat162float(h3));
    size_t o = (size_t)f * DIMD + c4;
    *(uint2*)&g_AH0[o] = make_uint2(packbf2(h0, h1), packbf2(h2, h3));
    *(uint2*)&g_AL0[o] = make_uint2(packbf2(l0, l1), packbf2(l2, l3));
}

// ---------------------------------------------------------------------------
// Split-bf16 HMMA GEMM: out[M, N] = relu(in[M,512] @ Wt[N,512]^T + bias)
// BM=128 BN=128 BK=64, 256 threads (8 warps 2x4, warp tile 64x32),
// 3-stage cp.async pipeline, SW128 swizzled 128B K-major rows.
// 3 MMA products per tile: Ah*Bh + Ah*Bl + Al*Bh.
// ---------------------------------------------------------------------------
#define GSTAGE 65536              // Ah 16K | Al 16K | Bh 16K | Bl 16K
#define GSMEM  (3 * GSTAGE)
#define SWZC(row, c16) ((uint32_t)((row) * 128 + (((c16) * 16) ^ (((row) & 7) * 16))))

__global__ __launch_bounds__(256, 1)
void gemm_mma_kernel(int selInH, int selInL, int selWH, int selWL,
                     const float* __restrict__ bias,
                     int selOutH, int selOutL, int Ncols)
{
    extern __shared__ char smem[];
    const uint32_t sb = smem_u32(smem);
    const int tid  = threadIdx.x;
    const int lane = tid & 31;
    const int warp = tid >> 5;
    const int warpM = (warp >> 2) * 64;   // 0 / 64
    const int warpN = (warp & 3) * 32;    // 0..96
    const size_t mBase = (size_t)blockIdx.y * 128;
    const size_t nBase = (size_t)blockIdx.x * 128;

    const __nv_bfloat16* __restrict__ inH = bsel(selInH);
    const __nv_bfloat16* __restrict__ inL = bsel(selInL);
    const __nv_bfloat16* __restrict__ wH  = bsel(selWH);
    const __nv_bfloat16* __restrict__ wL  = bsel(selWL);

    // ldmatrix per-lane geometry
    const int aRow   = (lane & 7) + ((lane >> 3) & 1) * 8;   // row within 16
    const int aColSl = lane >> 4;                            // 0/1 (16B col)
    const int bRow   = lane & 7;
    const int bColSl = (lane >> 3) & 1;

    float acc[4][4][4];
    #pragma unroll
    for (int i = 0; i < 4; i++)
        #pragma unroll
        for (int j = 0; j < 4; j++)
            #pragma unroll
            for (int q = 0; q < 4; q++) acc[i][j][q] = 0.0f;

    auto load_stage = [&](int c, int s) {
        uint32_t base = sb + s * GSTAGE;
        #pragma unroll
        for (int i = 0; i < 4; i++) {
            int ch = tid + i * 256;          // 0..1023
            int r = ch >> 3, c16 = ch & 7;
            uint32_t sw = SWZC(r, c16);
            size_t ga = (mBase + r) * 512 + (size_t)c * 64 + c16 * 8;
            size_t gb = (nBase + r) * 512 + (size_t)c * 64 + c16 * 8;
            cp16(base + sw,         inH + ga);
            cp16(base + 16384 + sw, inL + ga);
            cp16(base + 32768 + sw, wH + gb);
            cp16(base + 49152 + sw, wL + gb);
        }
        CP_COMMIT();
    };

    load_stage(0, 0);
    load_stage(1, 1);

    #pragma unroll 1
    for (int c = 0; c < 8; c++) {
        if (c < 7) { CP_WAIT(1); } else { CP_WAIT(0); }
        __syncthreads();
        if (c + 2 < 8) load_stage(c + 2, (c + 2) % 3);

        const uint32_t aBh = sb + (c % 3) * GSTAGE;
        const uint32_t aBl = aBh + 16384;
        const uint32_t bBh = aBh + 32768;
        const uint32_t bBl = aBh + 49152;

        #pragma unroll
        for (int ks = 0; ks < 4; ks++) {
            uint32_t ah[4][4], al[4][4];
            const int cA = ks * 2 + aColSl;
            #pragma unroll
            for (int i = 0; i < 4; i++) {
                int row = warpM + i * 16 + aRow;
                uint32_t off = SWZC(row, cA);
                ldmx4(ah[i], aBh + off);
                ldmx4(al[i], aBl + off);
            }
            uint32_t bh[4][2], bl[4][2];
            const int cB = ks * 2 + bColSl;
            #pragma unroll
            for (int j = 0; j < 4; j++) {
                int row = warpN + j * 8 + bRow;
                uint32_t off = SWZC(row, cB);
                ldmx2(bh[j], bBh + off);
                ldmx2(bl[j], bBl + off);
            }
            #pragma unroll
            for (int i = 0; i < 4; i++)
                #pragma unroll
                for (int j = 0; j < 4; j++) {
                    mma16816(acc[i][j], ah[i], bh[j]);
                    mma16816(acc[i][j], ah[i], bl[j]);
                    mma16816(acc[i][j], al[i], bh[j]);
                }
        }
    }

    // ---- epilogue: bias + relu + hi/lo split, direct global stores ----
    __nv_bfloat16* __restrict__ oH = bsel(selOutH);
    __nv_bfloat16* __restrict__ oL = bsel(selOutL);
    const int colq = (lane & 3) * 2;
    const int rowq = lane >> 2;

    #pragma unroll
    for (int j = 0; j < 4; j++) {
        size_t col = nBase + warpN + j * 8 + colq;
        float b0 = __ldg(&bias[col]);
        float b1 = __ldg(&bias[col + 1]);
        #pragma unroll
        for (int i = 0; i < 4; i++) {
            size_t row0 = mBase + warpM + i * 16 + rowq;
            size_t row1 = row0 + 8;
            float v00 = fmaxf(acc[i][j][0] + b0, 0.0f);
            float v01 = fmaxf(acc[i][j][1] + b1, 0.0f);
            float v10 = fmaxf(acc[i][j][2] + b0, 0.0f);
            float v11 = fmaxf(acc[i][j][3] + b1, 0.0f);
            __nv_bfloat16 h00 = __float2bfloat16(v00);
            __nv_bfloat16 h01 = __float2bfloat16(v01);
            __nv_bfloat16 h10 = __float2bfloat16(v10);
            __nv_bfloat16 h11 = __float2bfloat16(v11);
            __nv_bfloat16 l00 = __float2bfloat16(v00 - __bfloat162float(h00));
            __nv_bfloat16 l01 = __float2bfloat16(v01 - __bfloat162float(h01));
            __nv_bfloat16 l10 = __float2bfloat16(v10 - __bfloat162float(h10));
            __nv_bfloat16 l11 = __float2bfloat16(v11 - __bfloat162float(h11));
            *(uint32_t*)&oH[row0 * Ncols + col] = packbf2(h00, h01);
            *(uint32_t*)&oH[row1 * Ncols + col] = packbf2(h10, h11);
            *(uint32_t*)&oL[row0 * Ncols + col] = packbf2(l00, l01);
            *(uint32_t*)&oL[row1 * Ncols + col] = packbf2(l10, l11);
        }
    }
}

// ---------------------------------------------------------------------------
// out12 = (h3_hi + h3_lo) @ W4 + b4
// ---------------------------------------------------------------------------
__global__ __launch_bounds__(128)
void out12_kernel(const float* __restrict__ W4, const float* __restrict__ b4) {
    __shared__ float ws[256 * 12];
    for (int i = threadIdx.x; i < 256 * 12; i += blockDim.x) ws[i] = W4[i];
    __syncthreads();
    int r = blockIdx.x * blockDim.x + threadIdx.x;
    if (r >= N_FACES) return;
    const __nv_bfloat16* xh = g_H3H + (size_t)r * 256;
    const __nv_bfloat16* xl = g_H3L + (size_t)r * 256;
    float acc[12];
    #pragma unroll
    for (int n = 0; n < 12; n++) acc[n] = b4[n];
    for (int k = 0; k < 256; k += 8) {
        uint4 uh = *(const uint4*)&xh[k];
        uint4 ul = *(const uint4*)&xl[k];
        const uint32_t hu[4] = {uh.x, uh.y, uh.z, uh.w};
        const uint32_t lu[4] = {ul.x, ul.y, ul.z, ul.w};
        #pragma unroll
        for (int t = 0; t < 4; t++) {
            __nv_bfloat162 hb = *(const __nv_bfloat162*)&hu[t];
            __nv_bfloat162 lb = *(const __nv_bfloat162*)&lu[t];
            float v0 = __bfloat162float(hb.x) + __bfloat162float(lb.x);
            float v1 = __bfloat162float(hb.y) + __bfloat162float(lb.y);
            int kk = k + t * 2;
            #pragma unroll
            for (int n = 0; n < 12; n++) {
                acc[n] = fmaf(v0, ws[kk * 12 + n], acc[n]);
                acc[n] = fmaf(v1, ws[(kk + 1) * 12 + n], acc[n]);
            }
        }
    }
    #pragma unroll
    for (int n = 0; n < 12; n++) g_out12[(size_t)r * 12 + n] = acc[n];
}

// ---------------------------------------------------------------------------
// 3x3 Jacobi + special procrustes + transform + segment atomics
// ---------------------------------------------------------------------------
__device__ __forceinline__ void jrot(float A[3][3], float V[3][3],
                                     int p, int q, int r) {
    float apq = A[p][q];
    if (fabsf(apq) < 1e-20f) return;
    float tau = (A[q][q] - A[p][p]) / (2.0f * apq);
    float t = copysignf(1.0f, tau) / (fabsf(tau) + sqrtf(1.0f + tau * tau));
    float c = rsqrtf(1.0f + t * t);
    float s = t * c;
    A[p][p] -= t * apq;
    A[q][q] += t * apq;
    A[p][q] = 0.0f; A[q][p] = 0.0f;
    float arp = A[r][p], arq = A[r][q];
    A[r][p] = c * arp - s * arq; A[p][r] = A[r][p];
    A[r][q] = s * arp + c * arq; A[q][r] = A[r][q];
    #pragma unroll
    for (int k = 0; k < 3; k++) {
        float vkp = V[k][p], vkq = V[k][q];
        V[k][p] = c * vkp - s * vkq;
        V[k][q] = s * vkp + c * vkq;
    }
}

__device__ __forceinline__ void cross3(const float a[3], const float b[3], float o[3]) {
    o[0] = a[1] * b[2] - a[2] * b[1];
    o[1] = a[2] * b[0] - a[0] * b[2];
    o[2] = a[0] * b[1] - a[1] * b[0];
}

__global__ __launch_bounds__(256)
void procrustes_kernel(const float* __restrict__ verts,
                       const int*   __restrict__ faces,
                       float* __restrict__ out) {
    int f = blockIdx.x * blockDim.x + threadIdx.x;
    if (f >= N_FACES) return;

    float o[12];
    #pragma unroll
    for (int i = 0; i < 12; i++) o[i] = g_out12[(size_t)f * 12 + i];

    float m[3][3];
    #pragma unroll
    for (int i = 0; i < 3; i++)
        #pragma unroll
        for (int j = 0; j < 3; j++) m[i][j] = o[3 * i + j];

    float fr = 0.0f;
    #pragma unroll
    for (int i = 0; i < 3; i++)
        #pragma unroll
        for (int j = 0; j < 3; j++) fr += m[i][j] * m[i][j];
    float inv = rsqrtf(fmaxf(fr, 1e-30f));
    #pragma unroll
    for (int i = 0; i < 3; i++)
        #pragma unroll
        for (int j = 0; j < 3; j++) m[i][j] *= inv;

    float A[3][3];
    #pragma unroll
    for (int i = 0; i < 3; i++)
        #pragma unroll
        for (int j = 0; j < 3; j++) {
            float s = 0.0f;
            #pragma unroll
            for (int k = 0; k < 3; k++) s += m[k][i] * m[k][j];
            A[i][j] = s;
        }
    float V[3][3] = {{1,0,0},{0,1,0},{0,0,1}};

    #pragma unroll
    for (int sweep = 0; sweep < 6; sweep++) {
        jrot(A, V, 0, 1, 2);
        jrot(A, V, 0, 2, 1);
        jrot(A, V, 1, 2, 0);
    }

    float w0 = A[0][0], w1 = A[1][1], w2 = A[2][2];
    int imax = (w0 >= w1) ? (w0 >= w2 ? 0 : 2) : (w1 >= w2 ? 1 : 2);
    int imin = (w0 <= w1) ? (w0 <= w2 ? 0 : 2) : (w1 <= w2 ? 1 : 2);
    if (imax == imin) imin = (imax + 1) % 3;
    int imid = 3 - imax - imin;

    float v1[3] = {V[0][imax], V[1][imax], V[2][imax]};
    float v2[3] = {V[0][imid], V[1][imid], V[2][imid]};

    float u1[3], u2[3];
    #pragma unroll
    for (int a = 0; a < 3; a++)
        u1[a] = m[a][0] * v1[0] + m[a][1] * v1[1] + m[a][2] * v1[2];
    float n1 = sqrtf(u1[0]*u1[0] + u1[1]*u1[1] + u1[2]*u1[2]);
    if (n1 > 1e-12f) {
        float in1 = 1.0f / n1;
        u1[0] *= in1; u1[1] *= in1; u1[2] *= in1;
    } else { u1[0] = 1.0f; u1[1] = 0.0f; u1[2] = 0.0f; }

    #pragma unroll
    for (int a = 0; a < 3; a++)
        u2[a] = m[a][0] * v2[0] + m[a][1] * v2[1] + m[a][2] * v2[2];
    float d = u2[0]*u1[0] + u2[1]*u1[1] + u2[2]*u1[2];
    u2[0] -= d * u1[0]; u2[1] -= d * u1[1]; u2[2] -= d * u1[2];
    float n2 = sqrtf(u2[0]*u2[0] + u2[1]*u2[1] + u2[2]*u2[2]);
    if (n2 > 1e-10f) {
        float in2 = 1.0f / n2;
        u2[0] *= in2; u2[1] *= in2; u2[2] *= in2;
    } else {
        float e[3] = {0.f, 0.f, 0.f};
        e[(fabsf(u1[0]) < 0.9f) ? 0 : 1] = 1.0f;
        cross3(u1, e, u2);
        float nn = rsqrtf(fmaxf(u2[0]*u2[0]+u2[1]*u2[1]+u2[2]*u2[2], 1e-30f));
        u2[0] *= nn; u2[1] *= nn; u2[2] *= nn;
    }

    float u3[3], v3[3];
    cross3(u1, u2, u3);
    cross3(v1, v2, v3);

    float R[3][3];
    #pragma unroll
    for (int a = 0; a < 3; a++)
        #pragma unroll
        for (int b = 0; b < 3; b++)
            R[a][b] = u1[a]*v1[b] + u2[a]*v2[b] + u3[a]*v3[b];

    float* rot_out = out + (size_t)(N_VERTS * 3) + (size_t)N_FACES * 9 + (size_t)f * 9;
    #pragma unroll
    for (int a = 0; a < 3; a++)
        #pragma unroll
        for (int b = 0; b < 3; b++)
            rot_out[a * 3 + b] = R[a][b];

    float t0 = o[9], t1 = o[10], t2 = o[11];
    float* tp_out = out + (size_t)(N_VERTS * 3) + (size_t)f * 9;
    #pragma unroll
    for (int j = 0; j < 3; j++) {
        int vi = faces[f * 3 + j];
        float p0 = verts[(size_t)vi * 3 + 0];
        float p1 = verts[(size_t)vi * 3 + 1];
        float p2 = verts[(size_t)vi * 3 + 2];
        float tpx = p0 * R[0][0] + p1 * R[1][0] + p2 * R[2][0] + t0;
        float tpy = p0 * R[0][1] + p1 * R[1][1] + p2 * R[2][1] + t1;
        float tpz = p0 * R[0][2] + p1 * R[1][2] + p2 * R[2][2] + t2;
        tp_out[j * 3 + 0] = tpx;
        tp_out[j * 3 + 1] = tpy;
        tp_out[j * 3 + 2] = tpz;
        atomicAdd(&g_summed[(size_t)vi * 3 + 0], tpx);
        atomicAdd(&g_summed[(size_t)vi * 3 + 1], tpy);
        atomicAdd(&g_summed[(size_t)vi * 3 + 2], tpz);
        atomicAdd(&g_counts[vi], 1.0f);
    }
}

__global__ void finalize_kernel(float* __restrict__ out) {
    int v = blockIdx.x * blockDim.x + threadIdx.x;
    if (v >= N_VERTS) return;
    float c = fmaxf(g_counts[v], 1.0f);
    float ic = 1.0f / c;
    out[(size_t)v * 3 + 0] = g_summed[(size_t)v * 3 + 0] * ic;
    out[(size_t)v * 3 + 1] = g_summed[(size_t)v * 3 + 1] * ic;
    out[(size_t)v * 3 + 2] = g_summed[(size_t)v * 3 + 2] * ic;
}

// ---------------------------------------------------------------------------
extern "C" void kernel_launch(void* const* d_in, const int* in_sizes, int n_in,
                              void* d_out, int out_size) {
    const float* verts    = (const float*)d_in[0];
    const float* features = (const float*)d_in[1];
    const int*   faces    = (const int*)  d_in[2];
    const float* W1 = (const float*)d_in[3];
    const float* b1 = (const float*)d_in[4];
    const float* W2 = (const float*)d_in[5];
    const float* b2 = (const float*)d_in[6];
    const float* W3 = (const float*)d_in[7];
    const float* b3 = (const float*)d_in[8];
    const float* W4 = (const float*)d_in[9];
    const float* b4 = (const float*)d_in[10];
    float* out = (float*)d_out;

    (void)in_sizes; (void)n_in; (void)out_size;

    static int smem_set = 0;
    if (!smem_set) {
        cudaFuncSetAttribute(gemm_mma_kernel,
                             cudaFuncAttributeMaxDynamicSharedMemorySize,
                             GSMEM);
        smem_set = 1;
    }

    zero_kernel<<<(N_VERTS * 3 + 255) / 256, 256>>>();

    convert_w<<<(512 * 512 + 255) / 256, 256>>>(W1, 6, 7, 512);
    convert_w<<<(512 * 512 + 255) / 256, 256>>>(W2, 8, 9, 512);
    convert_w<<<(256 * 512 + 255) / 256, 256>>>(W3, 10, 11, 256);

    {
        int total = N_FACES * 128;
        gather_kernel<<<(total + 255) / 256, 256>>>(features, faces);
    }

    const int MB = MPAD / 128;   // 1563

    // h1 = relu(A0 @ W1t^T + b1) -> A1   (N=512: 4 x 128-col blocks)
    gemm_mma_kernel<<<dim3(4, MB), 256, GSMEM>>>(0, 1, 6, 7, b1, 2, 3, 512);
    // h2 = relu(A1 @ W2t^T + b2) -> A0
    gemm_mma_kernel<<<dim3(4, MB), 256, GSMEM>>>(2, 3, 8, 9, b2, 0, 1, 512);
    // h3 = relu(A0 @ W3t^T + b3) -> H3  (N=256: 2 blocks)
    gemm_mma_kernel<<<dim3(2, MB), 256, GSMEM>>>(0, 1, 10, 11, b3, 4, 5, 256);

    out12_kernel<<<(N_FACES + 127) / 128, 128>>>(W4, b4);

    procrustes_kernel<<<(N_FACES + 255) / 256, 256>>>(verts, faces, out);

    finalize_kernel<<<(N_VERTS + 255) / 256, 256>>>(out);
}